// round 8
// baseline (speedup 1.0000x reference)
#include <cuda_runtime.h>
#include <cstdint>

#define BATCH 512
#define TLEN  512
#define S     64
#define NEG_INF -10000.0f
#define NTHR  128      // tid = 2*n + h ; n = next tag, h = prev half
#define RD    8        // backtrace ring depth (prefetch distance 7)

typedef unsigned long long ull;

// vmax history: [b][t-1][n], pre-feat step maxima. 512*511*64*4 = 66.98 MB.
__device__ __align__(16) float g_vmax[(size_t)BATCH * (TLEN - 1) * S];

__device__ __forceinline__ ull ADD2(ull a, ull b) {
    ull r; asm("add.rn.f32x2 %0, %1, %2;" : "=l"(r) : "l"(a), "l"(b)); return r;
}
// max of the two packed halves; mov.b64 pair split is register aliasing (0 instr).
__device__ __forceinline__ float PMAX(ull v) {
    unsigned int l, h;
    asm("mov.b64 {%0,%1}, %2;" : "=r"(l), "=r"(h) : "l"(v));
    return fmaxf(__uint_as_float(l), __uint_as_float(h));
}

__global__ __launch_bounds__(NTHR) void viterbi_all(
    const float* __restrict__ logits,       // (B, T, S)
    const float* __restrict__ masks,        // (B, T)
    const float* __restrict__ transitions,  // (S, S) [next, prev]
    float* __restrict__ out)                // [0,B): path_score ; [B,...): best_seq
{
    const int b    = blockIdx.x;
    const int tid  = threadIdx.x;
    const int n    = tid >> 1;    // next tag 0..63
    const int h    = tid & 1;     // prev half 0..1
    const int lane = tid & 31;
    const int warp = tid >> 5;

    __shared__ __align__(16) float fvbuf[2][S];
    __shared__ __align__(16) float smask[TLEN];
    __shared__ __align__(16) float tr_s[S * S];     // full transitions (16 KB)
    __shared__ __align__(16) float ring_vm[RD][S];  // vmax rows (eq targets)
    __shared__ __align__(16) float ring_fv[RD][S];  // fv rows
    __shared__ unsigned char seq_s[TLEN];

    // ---- stage transitions (16 KB) + mask row (2 KB) ----
    {
        const float4* ts = (const float4*)transitions;
        float4* td = (float4*)tr_s;
        for (int i = tid; i < S * S / 4; i += NTHR) td[i] = ts[i];
        const float4* ms = (const float4*)(masks + (size_t)b * TLEN);
        ((float4*)smask)[tid] = ms[tid];
        if (h == 0) fvbuf[0][n] = (n == 0) ? 0.0f : NEG_INF;
    }
    __syncthreads();

    // ---- my 32 transitions (row n, half h) as 16 packed f32x2 ----
    ull tr2[16];
    {
        const ulonglong2* tp = (const ulonglong2*)(tr_s + n * S + h * 32);
#pragma unroll
        for (int i = 0; i < 8; i++) {
            ulonglong2 v = tp[i];
            tr2[2 * i] = v.x; tr2[2 * i + 1] = v.y;
        }
    }

    const float* lg = logits + (size_t)b * TLEN * S;
    float* vmb = g_vmax + (size_t)b * (TLEN - 1) * S;

    // ---- emission prefetch pipeline (depth 4) ----
    float fb[4];
#pragma unroll
    for (int i = 0; i < 4; i++) fb[i] = lg[(1 + i) * S + n];

    // =================== forward: max-only recursion ===================
#pragma unroll 4
    for (int t = 1; t < TLEN; t++) {
        float feat = fb[0];
        fb[0] = fb[1]; fb[1] = fb[2]; fb[2] = fb[3];
        int tpi = t + 4; if (tpi > TLEN - 1) tpi = TLEN - 1;
        fb[3] = lg[tpi * S + n];

        float m = smask[t];

        // my 32 fv values (8 broadcast LDS.128)
        const ulonglong2* fvp =
            (const ulonglong2*)(&fvbuf[(t - 1) & 1][32 * h]);

        // 4 independent chains of 8 prevs: 16 ADD2 (fma) + ~31 FMNMX (alu)
        float acc[4];
#pragma unroll
        for (int j = 0; j < 4; j++) {
            ulonglong2 F0 = fvp[2 * j + 0];
            ulonglong2 F1 = fvp[2 * j + 1];
            float m0 = PMAX(ADD2(F0.x, tr2[4 * j + 0]));
            float m1 = PMAX(ADD2(F0.y, tr2[4 * j + 1]));
            float m2 = PMAX(ADD2(F1.x, tr2[4 * j + 2]));
            float m3 = PMAX(ADD2(F1.y, tr2[4 * j + 3]));
            acc[j] = fmaxf(fmaxf(m0, m1), fmaxf(m2, m3));
        }
        float v = fmaxf(fmaxf(acc[0], acc[1]), fmaxf(acc[2], acc[3]));

        // merge the two prev halves (single shfl)
        v = fmaxf(v, __shfl_xor_sync(0xffffffffu, v, 1));

        if (h == 0) {
            vmb[(t - 1) * S + n] = v;                     // exact pre-feat max
            if (t == TLEN - 1 && n == S - 1) out[b] = v;  // path_score quirk
            fvbuf[t & 1][n] = __fadd_rn(v, __fmul_rn(feat, m));
        }
        __syncthreads();
    }

    // =================== backtrace: warp 0, equality search ===================
    if (warp == 0) {
        const int l = lane;

        // prefetch row i into ring slot i&(RD-1)
        auto pref = [&](int i) {
            int sl = i & (RD - 1);
            float2 fv;
            if (i == 0) {
                fv.x = (2 * l == 0) ? 0.0f : NEG_INF;
                fv.y = NEG_INF;
            } else {
                float2 vp = *(const float2*)(vmb + (size_t)(i - 1) * S + 2 * l);
                float2 ft = *(const float2*)(lg + (size_t)i * S + 2 * l);
                float mm = smask[i];
                fv.x = __fadd_rn(vp.x, __fmul_rn(ft.x, mm));
                fv.y = __fadd_rn(vp.y, __fmul_rn(ft.y, mm));
            }
            *(float2*)&ring_fv[sl][2 * l] = fv;
            float2 vm = *(const float2*)(vmb + (size_t)i * S + 2 * l);
            *(float2*)&ring_vm[sl][2 * l] = vm;
        };

        for (int j = 0; j < RD - 1; j++) {
            int i = (TLEN - 2) - j;
            if (i >= 0) pref(i);
        }
        __syncwarp();

        float2 fv_cur = *(const float2*)&ring_fv[(TLEN - 2) & (RD - 1)][2 * l];

        // lowest p with fv_cur[p] + tr[tag][p] == vmax_hist[i][tag]
        auto eq_step = [&](int i, int tag) -> int {
            float tgt = ring_vm[i & (RD - 1)][tag];
            float2 trp = *(const float2*)(tr_s + tag * S + 2 * l);
            float c0 = __fadd_rn(fv_cur.x, trp.x);
            float c1 = __fadd_rn(fv_cur.y, trp.y);
            unsigned m0 = __ballot_sync(0xffffffffu, c0 == tgt);
            unsigned m1 = __ballot_sync(0xffffffffu, c1 == tgt);
            int p0 = m0 ? ((__ffs(m0) - 1) << 1) : 1000;
            int p1 = m1 ? (((__ffs(m1) - 1) << 1) + 1) : 1000;
            int p = p0 < p1 ? p0 : p1;
            return p & 63;
        };

        // torch quirk: seed from bp(T-2, S-1); last table applied twice
        int tag = eq_step(TLEN - 2, S - 1);
        for (int i = TLEN - 2; i >= 0; i--) {
            if (l == 0) seq_s[i] = (unsigned char)tag;
            int nt = eq_step(i, tag);
            int ip = i - (RD - 1);
            if (ip >= 0) pref(ip);
            __syncwarp();
            if (i > 0)
                fv_cur = *(const float2*)&ring_fv[(i - 1) & (RD - 1)][2 * l];
            tag = nt;
        }
    }
    __syncthreads();

    // ---- coalesced output of the sequence ----
    float* o = out + BATCH + (size_t)b * (TLEN - 1);
    for (int i = tid; i < TLEN - 1; i += NTHR) o[i] = (float)seq_s[i];
}

extern "C" void kernel_launch(void* const* d_in, const int* in_sizes, int n_in,
                              void* d_out, int out_size)
{
    const float* logits      = (const float*)d_in[0];
    const float* masks       = (const float*)d_in[1];
    const float* transitions = (const float*)d_in[2];
    float* out = (float*)d_out;

    viterbi_all<<<BATCH, NTHR>>>(logits, masks, transitions, out);
}

// round 10
// speedup vs baseline: 1.4317x; 1.4317x over previous
#include <cuda_runtime.h>
#include <cstdint>

#define BATCH 512
#define TLEN  512
#define S     64
#define NEG_INF -10000.0f
#define NTHR  128      // tid = 2*n + h ; n = next tag, h = prev half
#define RD    8        // backtrace ring depth

typedef unsigned long long ull;

// vmax history: [b][t-1][n], pre-feat step maxima. 512*511*64*4 = 66.98 MB.
__device__ __align__(16) float g_vmax[(size_t)BATCH * (TLEN - 1) * S];

__device__ __forceinline__ ull ADD2(ull a, ull b) {
    ull r; asm("add.rn.f32x2 %0, %1, %2;" : "=l"(r) : "l"(a), "l"(b)); return r;
}
// max of packed halves; mov.b64 pair split is register aliasing (0 instr).
__device__ __forceinline__ float PMAX(ull v) {
    unsigned int l, h;
    asm("mov.b64 {%0,%1}, %2;" : "=r"(l), "=r"(h) : "l"(v));
    return fmaxf(__uint_as_float(l), __uint_as_float(h));
}

__global__ __launch_bounds__(NTHR) void viterbi_all(
    const float* __restrict__ logits,       // (B, T, S)
    const float* __restrict__ masks,        // (B, T)
    const float* __restrict__ transitions,  // (S, S) [next, prev]
    float* __restrict__ out)                // [0,B): path_score ; [B,...): best_seq
{
    const int b    = blockIdx.x;
    const int tid  = threadIdx.x;
    const int n    = tid >> 1;    // next tag 0..63
    const int h    = tid & 1;     // prev half 0..1
    const int lane = tid & 31;
    const int warp = tid >> 5;

    __shared__ __align__(16) float fvbuf[2][S];
    __shared__ __align__(16) float smask[TLEN];
    __shared__ __align__(16) float tr_s[S * S];       // 16 KB
    __shared__ __align__(16) float vm_ring[32][S];    // 8 KB vmax ring
    __shared__ __align__(16) float ring_vm[RD][S];    // backtrace eq targets
    __shared__ __align__(16) float ring_fv[RD][S];    // backtrace fv rows
    __shared__ unsigned char seq_s[TLEN];

    // ---- stage transitions (16 KB) + mask row (2 KB) ----
    {
        const float4* ts = (const float4*)transitions;
        float4* td = (float4*)tr_s;
        for (int i = tid; i < S * S / 4; i += NTHR) td[i] = ts[i];
        const float4* ms = (const float4*)(masks + (size_t)b * TLEN);
        ((float4*)smask)[tid] = ms[tid];
        if (h == 0) fvbuf[0][n] = (n == 0) ? 0.0f : NEG_INF;
    }
    __syncthreads();

    // ---- my 32 transitions (row n, half h) as 16 packed f32x2 ----
    ull tr2[16];
    {
        const ulonglong2* tp = (const ulonglong2*)(tr_s + n * S + h * 32);
#pragma unroll
        for (int i = 0; i < 8; i++) {
            ulonglong2 v = tp[i];
            tr2[2 * i] = v.x; tr2[2 * i + 1] = v.y;
        }
    }

    const float* lg = logits + (size_t)b * TLEN * S;
    float* vmb = g_vmax + (size_t)b * (TLEN - 1) * S;

    // ---- emission prefetch pipeline (depth 4) ----
    float fb[4];
#pragma unroll
    for (int i = 0; i < 4; i++) fb[i] = lg[(1 + i) * S + n];

    // ============ forward: max-only; vmax -> shared ring, burst flush ============
#pragma unroll 4
    for (int t = 1; t < TLEN; t++) {
        float feat = fb[0];
        fb[0] = fb[1]; fb[1] = fb[2]; fb[2] = fb[3];
        int tpi = t + 4; if (tpi > TLEN - 1) tpi = TLEN - 1;
        fb[3] = lg[tpi * S + n];

        float m = smask[t];

        const ulonglong2* fvp =
            (const ulonglong2*)(&fvbuf[(t - 1) & 1][32 * h]);

        float acc[4];
#pragma unroll
        for (int j = 0; j < 4; j++) {
            ulonglong2 F0 = fvp[2 * j + 0];
            ulonglong2 F1 = fvp[2 * j + 1];
            float m0 = PMAX(ADD2(F0.x, tr2[4 * j + 0]));
            float m1 = PMAX(ADD2(F0.y, tr2[4 * j + 1]));
            float m2 = PMAX(ADD2(F1.x, tr2[4 * j + 2]));
            float m3 = PMAX(ADD2(F1.y, tr2[4 * j + 3]));
            acc[j] = fmaxf(fmaxf(m0, m1), fmaxf(m2, m3));
        }
        float v = fmaxf(fmaxf(acc[0], acc[1]), fmaxf(acc[2], acc[3]));
        v = fmaxf(v, __shfl_xor_sync(0xffffffffu, v, 1));  // merge halves

        const int r = t - 1;
        if (h == 0) {
            vm_ring[r & 31][n] = v;                         // STS only
            fvbuf[t & 1][n] = __fadd_rn(v, __fmul_rn(feat, m));
        }
        __syncthreads();

        // cooperative burst flush of a finished 16-row group (plain STG.128)
        if ((r & 15) == 15) {
            const int base = r - 15;
            const float4* src = (const float4*)&vm_ring[base & 31][0];
            float4* dst = (float4*)(vmb + (size_t)base * S);
            dst[tid]       = src[tid];         // 16 rows * 16 f4 = 256 f4
            dst[tid + 128] = src[tid + 128];
        }
    }

    // tail flush: rows 496..510 (15 rows = 240 float4)
    {
        const int base = 496;
        const float4* src = (const float4*)&vm_ring[base & 31][0];
        float4* dst = (float4*)(vmb + (size_t)base * S);
        for (int i = tid; i < 240; i += NTHR) dst[i] = src[i];
    }
    // path_score quirk: pre-feat vmax at last step, next == S-1
    if (tid == 0) out[b] = vm_ring[(TLEN - 2) & 31][S - 1];
    __syncthreads();

    // =================== backtrace: warp 0, equality search ===================
    if (warp == 0) {
        const int l = lane;

        auto pref = [&](int i) {
            int sl = i & (RD - 1);
            float2 fv;
            if (i == 0) {
                fv.x = (2 * l == 0) ? 0.0f : NEG_INF;
                fv.y = NEG_INF;
            } else {
                float2 vp = *(const float2*)(vmb + (size_t)(i - 1) * S + 2 * l);
                float2 ft = *(const float2*)(lg + (size_t)i * S + 2 * l);
                float mm = smask[i];
                fv.x = __fadd_rn(vp.x, __fmul_rn(ft.x, mm));
                fv.y = __fadd_rn(vp.y, __fmul_rn(ft.y, mm));
            }
            *(float2*)&ring_fv[sl][2 * l] = fv;
            float2 vm = *(const float2*)(vmb + (size_t)i * S + 2 * l);
            *(float2*)&ring_vm[sl][2 * l] = vm;
        };

        for (int j = 0; j < RD - 1; j++) {
            int i = (TLEN - 2) - j;
            if (i >= 0) pref(i);
        }
        __syncwarp();

        float2 fv_cur = *(const float2*)&ring_fv[(TLEN - 2) & (RD - 1)][2 * l];

        // lowest p with fv_cur[p] + tr[tag][p] == vmax_hist[i][tag]
        auto eq_step = [&](int i, int tag) -> int {
            float tgt = ring_vm[i & (RD - 1)][tag];
            float2 trp = *(const float2*)(tr_s + tag * S + 2 * l);
            float c0 = __fadd_rn(fv_cur.x, trp.x);
            float c1 = __fadd_rn(fv_cur.y, trp.y);
            unsigned m0 = __ballot_sync(0xffffffffu, c0 == tgt);
            unsigned m1 = __ballot_sync(0xffffffffu, c1 == tgt);
            int p0 = m0 ? ((__ffs(m0) - 1) << 1) : 1000;
            int p1 = m1 ? (((__ffs(m1) - 1) << 1) + 1) : 1000;
            int p = p0 < p1 ? p0 : p1;
            return p & 63;
        };

        // torch quirk: seed from bp(T-2, S-1); last table applied twice
        int tag = eq_step(TLEN - 2, S - 1);
        for (int i = TLEN - 2; i >= 0; i--) {
            if (l == 0) seq_s[i] = (unsigned char)tag;
            int nt = eq_step(i, tag);
            int ip = i - (RD - 1);
            if (ip >= 0) pref(ip);
            __syncwarp();
            if (i > 0)
                fv_cur = *(const float2*)&ring_fv[(i - 1) & (RD - 1)][2 * l];
            tag = nt;
        }
    }
    __syncthreads();

    // ---- coalesced output ----
    float* o = out + BATCH + (size_t)b * (TLEN - 1);
    for (int i = tid; i < TLEN - 1; i += NTHR) o[i] = (float)seq_s[i];
}

extern "C" void kernel_launch(void* const* d_in, const int* in_sizes, int n_in,
                              void* d_out, int out_size)
{
    const float* logits      = (const float*)d_in[0];
    const float* masks       = (const float*)d_in[1];
    const float* transitions = (const float*)d_in[2];
    float* out = (float*)d_out;

    viterbi_all<<<BATCH, NTHR>>>(logits, masks, transitions, out);
}

// round 11
// speedup vs baseline: 1.7909x; 1.2508x over previous
#include <cuda_runtime.h>
#include <cstdint>

#define BATCH 512
#define TLEN  512
#define S     64
#define NEG_INF -10000.0f
#define NTHR  128          // 4 independent warps; warp = one batch
#define WPB   4
#define RD    8            // backtrace ring depth

typedef unsigned long long ull;

// vmax history: [b][t-1][n], pre-feat step maxima. 512*511*64*4 = 66.98 MB.
__device__ __align__(16) float g_vmax[(size_t)BATCH * (TLEN - 1) * S];

__device__ __forceinline__ ull ADD2(ull a, ull b) {
    ull r; asm("add.rn.f32x2 %0, %1, %2;" : "=l"(r) : "l"(a), "l"(b)); return r;
}
// max of packed halves; mov.b64 split is register aliasing (0 instr).
__device__ __forceinline__ float PMAX(ull v) {
    unsigned int l, h;
    asm("mov.b64 {%0,%1}, %2;" : "=r"(l), "=r"(h) : "l"(v));
    return fmaxf(__uint_as_float(l), __uint_as_float(h));
}

__global__ __launch_bounds__(NTHR, 1) void viterbi_all(
    const float* __restrict__ logits,       // (B, T, S)
    const float* __restrict__ masks,        // (B, T)
    const float* __restrict__ transitions,  // (S, S) [next, prev]
    float* __restrict__ out)                // [0,B): path_score ; [B,...): best_seq
{
    const int tid = threadIdx.x;
    const int l   = tid & 31;          // lane
    const int w   = tid >> 5;          // warp -> batch slot (SMSP w)
    const int b   = blockIdx.x * WPB + w;

    __shared__ __align__(16) float tr_s[S * S];          // 16 KB (all warps)
    __shared__ __align__(16) float fvbuf[WPB][2][S];     // 2 KB
    __shared__ __align__(16) float smask[WPB][TLEN];     // 8 KB
    __shared__ __align__(16) float ring_vm[WPB][RD][S];  // 8 KB
    __shared__ __align__(16) float ring_fv[WPB][RD][S];  // 8 KB
    __shared__ unsigned char seq_s[WPB][TLEN];           // 2 KB

    // ---- stage transitions (block-cooperative) + per-warp mask row ----
    {
        const float4* ts = (const float4*)transitions;
        float4* td = (float4*)tr_s;
        for (int i = tid; i < S * S / 4; i += NTHR) td[i] = ts[i];
        const float4* ms = (const float4*)(masks + (size_t)b * TLEN);
        float4* md = (float4*)smask[w];
#pragma unroll
        for (int i = 0; i < 4; i++) md[l + 32 * i] = ms[l + 32 * i];
        fvbuf[w][0][l]      = (l == 0) ? 0.0f : NEG_INF;
        fvbuf[w][0][l + 32] = NEG_INF;
    }
    __syncthreads();   // once, before the recursion

    // ---- my two transition rows (tags l and l+32) in registers: 64 ull ----
    ull trA[32], trB[32];
    {
        const ulonglong2* ta = (const ulonglong2*)(tr_s + l * S);
        const ulonglong2* tb = (const ulonglong2*)(tr_s + (l + 32) * S);
#pragma unroll
        for (int i = 0; i < 16; i++) {
            ulonglong2 va = ta[i]; trA[2 * i] = va.x; trA[2 * i + 1] = va.y;
            ulonglong2 vb = tb[i]; trB[2 * i] = vb.x; trB[2 * i + 1] = vb.y;
        }
    }

    const float* lg = logits + (size_t)b * TLEN * S;
    float* vmb = g_vmax + (size_t)b * (TLEN - 1) * S;

    // ---- emission prefetch (depth 4) for both tags ----
    float fa[4], fbr[4];
#pragma unroll
    for (int i = 0; i < 4; i++) {
        fa[i]  = lg[(1 + i) * S + l];
        fbr[i] = lg[(1 + i) * S + l + 32];
    }

    // ============ forward: one warp, no block barrier ============
#pragma unroll 2
    for (int t = 1; t < TLEN; t++) {
        float featA = fa[0], featB = fbr[0];
        fa[0] = fa[1]; fa[1] = fa[2]; fa[2] = fa[3];
        fbr[0] = fbr[1]; fbr[1] = fbr[2]; fbr[2] = fbr[3];
        int tpi = t + 4; if (tpi > TLEN - 1) tpi = TLEN - 1;
        fa[3]  = lg[tpi * S + l];
        fbr[3] = lg[tpi * S + l + 32];

        float m = smask[w][t];

        const ulonglong2* fvp =
            (const ulonglong2*)fvbuf[w][(t - 1) & 1];   // broadcast reads

        float accA[4], accB[4];
#pragma unroll
        for (int j = 0; j < 4; j++) {
            ulonglong2 q0 = fvp[4 * j + 0];
            ulonglong2 q1 = fvp[4 * j + 1];
            ulonglong2 q2 = fvp[4 * j + 2];
            ulonglong2 q3 = fvp[4 * j + 3];
            int k = 8 * j;
            float a0 = PMAX(ADD2(q0.x, trA[k + 0]));
            float a1 = PMAX(ADD2(q0.y, trA[k + 1]));
            float a2 = PMAX(ADD2(q1.x, trA[k + 2]));
            float a3 = PMAX(ADD2(q1.y, trA[k + 3]));
            float a4 = PMAX(ADD2(q2.x, trA[k + 4]));
            float a5 = PMAX(ADD2(q2.y, trA[k + 5]));
            float a6 = PMAX(ADD2(q3.x, trA[k + 6]));
            float a7 = PMAX(ADD2(q3.y, trA[k + 7]));
            accA[j] = fmaxf(fmaxf(fmaxf(a0, a1), fmaxf(a2, a3)),
                            fmaxf(fmaxf(a4, a5), fmaxf(a6, a7)));
            float b0 = PMAX(ADD2(q0.x, trB[k + 0]));
            float b1 = PMAX(ADD2(q0.y, trB[k + 1]));
            float b2 = PMAX(ADD2(q1.x, trB[k + 2]));
            float b3 = PMAX(ADD2(q1.y, trB[k + 3]));
            float b4 = PMAX(ADD2(q2.x, trB[k + 4]));
            float b5 = PMAX(ADD2(q2.y, trB[k + 5]));
            float b6 = PMAX(ADD2(q3.x, trB[k + 6]));
            float b7 = PMAX(ADD2(q3.y, trB[k + 7]));
            accB[j] = fmaxf(fmaxf(fmaxf(b0, b1), fmaxf(b2, b3)),
                            fmaxf(fmaxf(b4, b5), fmaxf(b6, b7)));
        }
        float vA = fmaxf(fmaxf(accA[0], accA[1]), fmaxf(accA[2], accA[3]));
        float vB = fmaxf(fmaxf(accB[0], accB[1]), fmaxf(accB[2], accB[3]));

        const int r = t - 1;
        vmb[r * S + l]      = vA;        // fire-and-forget, no barrier drain
        vmb[r * S + l + 32] = vB;
        fvbuf[w][t & 1][l]      = __fadd_rn(vA, __fmul_rn(featA, m));
        fvbuf[w][t & 1][l + 32] = __fadd_rn(vB, __fmul_rn(featB, m));
        __syncwarp();                    // only sync in the recursion
        if (t == TLEN - 1 && l == 31) out[b] = vB;  // path_score quirk (tag 63)
    }

    // ============ backtrace: same warp, equality search ============
    {
        auto pref = [&](int i) {
            int sl = i & (RD - 1);
            float2 fv;
            if (i == 0) {
                fv.x = (2 * l == 0) ? 0.0f : NEG_INF;
                fv.y = NEG_INF;
            } else {
                float2 vp = *(const float2*)(vmb + (size_t)(i - 1) * S + 2 * l);
                float2 ft = *(const float2*)(lg + (size_t)i * S + 2 * l);
                float mm = smask[w][i];
                fv.x = __fadd_rn(vp.x, __fmul_rn(ft.x, mm));
                fv.y = __fadd_rn(vp.y, __fmul_rn(ft.y, mm));
            }
            *(float2*)&ring_fv[w][sl][2 * l] = fv;
            float2 vm = *(const float2*)(vmb + (size_t)i * S + 2 * l);
            *(float2*)&ring_vm[w][sl][2 * l] = vm;
        };

        for (int j = 0; j < RD - 1; j++) {
            int i = (TLEN - 2) - j;
            if (i >= 0) pref(i);
        }
        __syncwarp();

        float2 fv_cur = *(const float2*)&ring_fv[w][(TLEN - 2) & (RD - 1)][2 * l];

        // lowest p with fv_cur[p] + tr[tag][p] == vmax_hist[i][tag]
        auto eq_step = [&](int i, int tag) -> int {
            float tgt = ring_vm[w][i & (RD - 1)][tag];
            float2 trp = *(const float2*)(tr_s + tag * S + 2 * l);
            float c0 = __fadd_rn(fv_cur.x, trp.x);
            float c1 = __fadd_rn(fv_cur.y, trp.y);
            unsigned m0 = __ballot_sync(0xffffffffu, c0 == tgt);
            unsigned m1 = __ballot_sync(0xffffffffu, c1 == tgt);
            int p0 = m0 ? ((__ffs(m0) - 1) << 1) : 1000;
            int p1 = m1 ? (((__ffs(m1) - 1) << 1) + 1) : 1000;
            int p = p0 < p1 ? p0 : p1;
            return p & 63;
        };

        // torch quirk: seed from bp(T-2, S-1); last table applied twice
        int tag = eq_step(TLEN - 2, S - 1);
        for (int i = TLEN - 2; i >= 0; i--) {
            if (l == 0) seq_s[w][i] = (unsigned char)tag;
            int nt = eq_step(i, tag);
            int ip = i - (RD - 1);
            if (ip >= 0) pref(ip);
            __syncwarp();
            if (i > 0)
                fv_cur = *(const float2*)&ring_fv[w][(i - 1) & (RD - 1)][2 * l];
            tag = nt;
        }
    }
    __syncwarp();

    // ---- coalesced output of this warp's sequence ----
    float* o = out + BATCH + (size_t)b * (TLEN - 1);
    for (int i = l; i < TLEN - 1; i += 32) o[i] = (float)seq_s[w][i];
}

extern "C" void kernel_launch(void* const* d_in, const int* in_sizes, int n_in,
                              void* d_out, int out_size)
{
    const float* logits      = (const float*)d_in[0];
    const float* masks       = (const float*)d_in[1];
    const float* transitions = (const float*)d_in[2];
    float* out = (float*)d_out;

    viterbi_all<<<BATCH / WPB, NTHR>>>(logits, masks, transitions, out);
}